// round 1
// baseline (speedup 1.0000x reference)
#include <cuda_runtime.h>
#include <cuda_bf16.h>
#include <cstdint>

// Problem constants
#define Bb 128
#define Ss 128
#define Hh 1024
#define Ee 512
#define Vv 32000

// GEMM tile config
#define BM 128
#define BN 128
#define BK 16
#define SA 20   // padded smem row stride (floats)

// ---------------- scratch (device globals; no allocation allowed) ----------
__device__ __align__(256) float g_x[Bb * 2560];        // [embeds | a]  (E + 2H)
__device__ __align__(256) float g_c1[Bb * 3584];       // [h_new | a | embeds]
__device__ __align__(256) float g_hb[Bb * Hh];         // dh @ W1h^T + b1
__device__ __align__(256) float g_part[8 * (Ss * Bb)]; // per-nblock partial scores
__device__ __align__(256) float g_alpha[Ss * Bb];      // softmax weights [s][b]
__device__ __align__(256) float g_gx[Bb * 3 * Hh];
__device__ __align__(256) float g_gh[Bb * 3 * Hh];

// ---------------- helpers ---------------------------------------------------
__device__ __forceinline__ float to_tf32(float x) {
    uint32_t u;
    asm("cvt.rna.tf32.f32 %0, %1;" : "=r"(u) : "f"(x));
    return __uint_as_float(u);
}

__device__ __forceinline__ void mma_tf32(float* c,
                                         uint32_t a0, uint32_t a1, uint32_t a2, uint32_t a3,
                                         uint32_t b0, uint32_t b1) {
    asm volatile(
        "mma.sync.aligned.m16n8k8.row.col.f32.tf32.tf32.f32 "
        "{%0,%1,%2,%3}, {%4,%5,%6,%7}, {%8,%9}, {%0,%1,%2,%3};"
        : "+f"(c[0]), "+f"(c[1]), "+f"(c[2]), "+f"(c[3])
        : "r"(a0), "r"(a1), "r"(a2), "r"(a3), "r"(b0), "r"(b1));
}

// ---------------- generic tf32 GEMM: out[M,N] = A[M,K] @ Bw[N,K]^T ----------
// EPI 0: out[m*ldc+n] = acc + bias[n]
// EPI 1: (attention energy) partial[bx*M + m] = sum_n tanh(acc + hb[(m%128)*H + n]) * W2[n]
template <int EPI>
__global__ __launch_bounds__(256)
void gemm_tf32(const float* __restrict__ A, const float* __restrict__ Bw,
               const float* __restrict__ bias, float* __restrict__ out,
               int M, int N, int K, int lda, int ldb, int ldc,
               const float* __restrict__ hb, const float* __restrict__ W2) {
    __shared__ float As[2][BM * SA];
    __shared__ float Bs[2][BN * SA];
    __shared__ float red[BM][2];

    const int tid  = threadIdx.x;
    const int lane = tid & 31;
    const int wid  = tid >> 5;
    const int wm   = wid >> 1;   // 0..3  (32 rows each)
    const int wn   = wid & 1;    // 0..1  (64 cols each)
    const int r    = lane >> 2;
    const int q    = lane & 3;

    const int m0 = blockIdx.y * BM;
    const int n0 = blockIdx.x * BN;

    const int lrow = tid >> 2;        // 0..63
    const int lcol = (tid & 3) * 4;   // 0,4,8,12

    const float* Ag = A  + (size_t)(m0 + lrow) * lda + lcol;
    const float* Bg = Bw + (size_t)(n0 + lrow) * ldb + lcol;

    float c[2][8][4];
#pragma unroll
    for (int i = 0; i < 2; i++)
#pragma unroll
        for (int j = 0; j < 8; j++)
#pragma unroll
            for (int k = 0; k < 4; k++) c[i][j][k] = 0.f;

    const int nK = K / BK;

    float4 ra0, ra1, rb0, rb1;
    // prologue: stage 0
    ra0 = *(const float4*)(Ag);
    ra1 = *(const float4*)(Ag + (size_t)64 * lda);
    rb0 = *(const float4*)(Bg);
    rb1 = *(const float4*)(Bg + (size_t)64 * ldb);
    {
        float* a = &As[0][lrow * SA + lcol];
        a[0] = to_tf32(ra0.x); a[1] = to_tf32(ra0.y); a[2] = to_tf32(ra0.z); a[3] = to_tf32(ra0.w);
        float* a2 = &As[0][(lrow + 64) * SA + lcol];
        a2[0] = to_tf32(ra1.x); a2[1] = to_tf32(ra1.y); a2[2] = to_tf32(ra1.z); a2[3] = to_tf32(ra1.w);
        float* b = &Bs[0][lrow * SA + lcol];
        b[0] = to_tf32(rb0.x); b[1] = to_tf32(rb0.y); b[2] = to_tf32(rb0.z); b[3] = to_tf32(rb0.w);
        float* b2 = &Bs[0][(lrow + 64) * SA + lcol];
        b2[0] = to_tf32(rb1.x); b2[1] = to_tf32(rb1.y); b2[2] = to_tf32(rb1.z); b2[3] = to_tf32(rb1.w);
    }
    __syncthreads();

    for (int kb = 0; kb < nK; kb++) {
        const int cur = kb & 1;
        if (kb + 1 < nK) {
            const int ko = (kb + 1) * BK;
            ra0 = *(const float4*)(Ag + ko);
            ra1 = *(const float4*)(Ag + (size_t)64 * lda + ko);
            rb0 = *(const float4*)(Bg + ko);
            rb1 = *(const float4*)(Bg + (size_t)64 * ldb + ko);
        }
#pragma unroll
        for (int ks = 0; ks < 2; ks++) {
            const int k0 = ks * 8;
            uint32_t af[2][4];
#pragma unroll
            for (int mf = 0; mf < 2; mf++) {
                const int mb = (wm * 32 + mf * 16) * SA;
                af[mf][0] = __float_as_uint(As[cur][mb + r * SA + k0 + q]);
                af[mf][1] = __float_as_uint(As[cur][mb + (r + 8) * SA + k0 + q]);
                af[mf][2] = __float_as_uint(As[cur][mb + r * SA + k0 + q + 4]);
                af[mf][3] = __float_as_uint(As[cur][mb + (r + 8) * SA + k0 + q + 4]);
            }
#pragma unroll
            for (int nf = 0; nf < 8; nf++) {
                const int nb = (wn * 64 + nf * 8 + r) * SA;
                uint32_t b0 = __float_as_uint(Bs[cur][nb + k0 + q]);
                uint32_t b1 = __float_as_uint(Bs[cur][nb + k0 + q + 4]);
#pragma unroll
                for (int mf = 0; mf < 2; mf++)
                    mma_tf32(c[mf][nf], af[mf][0], af[mf][1], af[mf][2], af[mf][3], b0, b1);
            }
        }
        if (kb + 1 < nK) {
            const int nxt = (kb + 1) & 1;
            float* a = &As[nxt][lrow * SA + lcol];
            a[0] = to_tf32(ra0.x); a[1] = to_tf32(ra0.y); a[2] = to_tf32(ra0.z); a[3] = to_tf32(ra0.w);
            float* a2 = &As[nxt][(lrow + 64) * SA + lcol];
            a2[0] = to_tf32(ra1.x); a2[1] = to_tf32(ra1.y); a2[2] = to_tf32(ra1.z); a2[3] = to_tf32(ra1.w);
            float* b = &Bs[nxt][lrow * SA + lcol];
            b[0] = to_tf32(rb0.x); b[1] = to_tf32(rb0.y); b[2] = to_tf32(rb0.z); b[3] = to_tf32(rb0.w);
            float* b2 = &Bs[nxt][(lrow + 64) * SA + lcol];
            b2[0] = to_tf32(rb1.x); b2[1] = to_tf32(rb1.y); b2[2] = to_tf32(rb1.z); b2[3] = to_tf32(rb1.w);
        }
        __syncthreads();
    }

    if (EPI == 0) {
#pragma unroll
        for (int mf = 0; mf < 2; mf++)
#pragma unroll
            for (int rr = 0; rr < 2; rr++) {
                const int mg = m0 + wm * 32 + mf * 16 + rr * 8 + r;
#pragma unroll
                for (int nf = 0; nf < 8; nf++) {
                    const int ng = n0 + wn * 64 + nf * 8 + q * 2;
                    out[(size_t)mg * ldc + ng]     = c[mf][nf][rr * 2 + 0] + bias[ng];
                    out[(size_t)mg * ldc + ng + 1] = c[mf][nf][rr * 2 + 1] + bias[ng + 1];
                }
            }
    } else {
        // energy epilogue: tanh(acc + hb[b,n]) * W2[n], reduce over this CTA's n-range
        float rs[2][2];
#pragma unroll
        for (int mf = 0; mf < 2; mf++)
#pragma unroll
            for (int rr = 0; rr < 2; rr++) {
                const int row = wm * 32 + mf * 16 + rr * 8 + r; // == b (m0 % 128 == 0)
                float acc = 0.f;
#pragma unroll
                for (int nf = 0; nf < 8; nf++) {
                    const int ng = n0 + wn * 64 + nf * 8 + q * 2;
                    const float h0 = hb[row * Hh + ng];
                    const float h1 = hb[row * Hh + ng + 1];
                    acc += tanhf(c[mf][nf][rr * 2 + 0] + h0) * W2[ng];
                    acc += tanhf(c[mf][nf][rr * 2 + 1] + h1) * W2[ng + 1];
                }
                rs[mf][rr] = acc;
            }
#pragma unroll
        for (int mf = 0; mf < 2; mf++)
#pragma unroll
            for (int rr = 0; rr < 2; rr++) {
                rs[mf][rr] += __shfl_xor_sync(0xffffffffu, rs[mf][rr], 1);
                rs[mf][rr] += __shfl_xor_sync(0xffffffffu, rs[mf][rr], 2);
            }
        if (q == 0) {
#pragma unroll
            for (int mf = 0; mf < 2; mf++)
#pragma unroll
                for (int rr = 0; rr < 2; rr++)
                    red[wm * 32 + mf * 16 + rr * 8 + r][wn] = rs[mf][rr];
        }
        __syncthreads();
        if (tid < BM)
            out[(size_t)blockIdx.x * M + m0 + tid] = red[tid][0] + red[tid][1];
    }
}

// ---------------- small kernels ---------------------------------------------
__global__ void k_embed(const int* __restrict__ tl, const float* __restrict__ emb,
                        float* __restrict__ x, float* __restrict__ c1) {
    const int b = blockIdx.x;
    const int e = threadIdx.x; // 512
    const float v = emb[(size_t)tl[b] * Ee + e];
    x[b * 2560 + e] = v;
    c1[b * 3584 + 3072 + e] = v;
}

__global__ void k_softmax(const float* __restrict__ part, float* __restrict__ alpha) {
    const int b = blockIdx.x;
    const int s = threadIdx.x; // 128
    float sc = 0.f;
#pragma unroll
    for (int p = 0; p < 8; p++) sc += part[p * (Ss * Bb) + s * Bb + b];
    __shared__ float sh[Ss];
    sh[s] = sc; __syncthreads();
    for (int off = 64; off > 0; off >>= 1) {
        if (s < off) sh[s] = fmaxf(sh[s], sh[s + off]);
        __syncthreads();
    }
    const float mx = sh[0]; __syncthreads();
    const float e = expf(sc - mx);
    sh[s] = e; __syncthreads();
    for (int off = 64; off > 0; off >>= 1) {
        if (s < off) sh[s] += sh[s + off];
        __syncthreads();
    }
    alpha[s * Bb + b] = e / sh[0];
}

__global__ void k_context(const float* __restrict__ enc, const float* __restrict__ alpha,
                          float* __restrict__ x, float* __restrict__ c1) {
    const int b = blockIdx.x;
    const int t = threadIdx.x; // 512
    float a0 = 0.f, a1 = 0.f, a2 = 0.f, a3 = 0.f;
    for (int s = 0; s < Ss; s++) {
        const float al = alpha[s * Bb + b];
        const float* e = enc + (size_t)(s * Bb + b) * 2048 + t;
        a0 += al * e[0];
        a1 += al * e[512];
        a2 += al * e[1024];
        a3 += al * e[1536];
    }
    x[b * 2560 + 512 + t]        = a0;  c1[b * 3584 + 1024 + t]        = a0;
    x[b * 2560 + 512 + 512 + t]  = a1;  c1[b * 3584 + 1024 + 512 + t]  = a1;
    x[b * 2560 + 512 + 1024 + t] = a2;  c1[b * 3584 + 1024 + 1024 + t] = a2;
    x[b * 2560 + 512 + 1536 + t] = a3;  c1[b * 3584 + 1024 + 1536 + t] = a3;
}

__global__ void k_gru(const float* __restrict__ dh, const float* __restrict__ gx,
                      const float* __restrict__ gh, float* __restrict__ hout,
                      float* __restrict__ c1) {
    const int b = blockIdx.x;
    const int h = threadIdx.x; // 1024
    const float xr = gx[b * 3072 + h],        hr = gh[b * 3072 + h];
    const float xz = gx[b * 3072 + 1024 + h], hz = gh[b * 3072 + 1024 + h];
    const float xn = gx[b * 3072 + 2048 + h], hn = gh[b * 3072 + 2048 + h];
    const float rg = 1.f / (1.f + expf(-(xr + hr)));
    const float zg = 1.f / (1.f + expf(-(xz + hz)));
    const float ng = tanhf(xn + rg * hn);
    const float hv = (1.f - zg) * ng + zg * dh[b * Hh + h];
    hout[b * Hh + h] = hv;
    c1[b * 3584 + h] = hv;
}

// ---------------- launch ----------------------------------------------------
extern "C" void kernel_launch(void* const* d_in, const int* in_sizes, int n_in,
                              void* d_out, int out_size) {
    const int*   tl   = (const int*)d_in[0];
    const float* dh   = (const float*)d_in[1];
    const float* enc  = (const float*)d_in[2];
    const float* emb  = (const float*)d_in[3];
    const float* W1   = (const float*)d_in[4];
    const float* b1   = (const float*)d_in[5];
    const float* W2   = (const float*)d_in[6];
    // d_in[7] = b2 (softmax-invariant, skipped)
    const float* Wih  = (const float*)d_in[8];
    const float* Whh  = (const float*)d_in[9];
    const float* bih  = (const float*)d_in[10];
    const float* bhh  = (const float*)d_in[11];
    const float* Wout = (const float*)d_in[12];
    const float* bout = (const float*)d_in[13];

    float* pred = (float*)d_out;                 // [128, 32000]
    float* hout = pred + (size_t)Bb * Vv;        // [128, 1024]

    float *x, *c1, *hb, *part, *alpha, *gx, *gh;
    cudaGetSymbolAddress((void**)&x,     g_x);
    cudaGetSymbolAddress((void**)&c1,    g_c1);
    cudaGetSymbolAddress((void**)&hb,    g_hb);
    cudaGetSymbolAddress((void**)&part,  g_part);
    cudaGetSymbolAddress((void**)&alpha, g_alpha);
    cudaGetSymbolAddress((void**)&gx,    g_gx);
    cudaGetSymbolAddress((void**)&gh,    g_gh);

    // 1) embeddings -> x[:, :512], c1[:, 3072:]
    k_embed<<<Bb, 512>>>(tl, emb, x, c1);

    // 2) hb = dh @ W1[:, 2048:3072]^T + b1   (M=128, N=1024, K=1024)
    gemm_tf32<0><<<dim3(Hh / BN, 1), 256>>>(dh, W1 + 2048, b1, hb,
                                            Bb, Hh, Hh, Hh, 3 * Hh, Hh, nullptr, nullptr);

    // 3) energy GEMM + fused tanh*W2 reduction (M=16384, N=1024, K=2048)
    //    grid.x = n-blocks (fastest) so co-resident CTAs share the enc A-band in L2
    gemm_tf32<1><<<dim3(Hh / BN, (Ss * Bb) / BM), 256>>>(enc, W1, nullptr, part,
                                                         Ss * Bb, Hh, 2 * Hh,
                                                         2 * Hh, 3 * Hh, 0, hb, W2);

    // 4) combine partials + softmax over s  -> alpha[s][b]
    k_softmax<<<Bb, Ss>>>(part, alpha);

    // 5) context a = sum_s alpha * enc -> x[:, 512:], c1[:, 1024:3072]
    k_context<<<Bb, 512>>>(enc, alpha, x, c1);

    // 6) gx = x @ Wih^T + bih   (M=128, N=3072, K=2560)
    gemm_tf32<0><<<dim3(3 * Hh / BN, 1), 256>>>(x, Wih, bih, gx,
                                                Bb, 3 * Hh, 2560, 2560, 2560, 3 * Hh,
                                                nullptr, nullptr);

    // 7) gh = dh @ Whh^T + bhh  (M=128, N=3072, K=1024)
    gemm_tf32<0><<<dim3(3 * Hh / BN, 1), 256>>>(dh, Whh, bhh, gh,
                                                Bb, 3 * Hh, Hh, Hh, Hh, 3 * Hh,
                                                nullptr, nullptr);

    // 8) GRU elementwise -> h_new (output tail) and c1[:, :1024]
    k_gru<<<Bb, Hh>>>(dh, gx, gh, hout, c1);

    // 9) pred = c1 @ Wout^T + bout  (M=128, N=32000, K=3584)
    gemm_tf32<0><<<dim3(Vv / BN, 1), 256>>>(c1, Wout, bout, pred,
                                            Bb, Vv, 3584, 3584, 3584, Vv,
                                            nullptr, nullptr);
}

// round 3
// speedup vs baseline: 1.5194x; 1.5194x over previous
#include <cuda_runtime.h>
#include <cuda_bf16.h>
#include <cstdint>

// Problem constants
#define Bb 128
#define Ss 128
#define Hh 1024
#define Ee 512
#define Vv 32000

// GEMM tile config
#define BM 128
#define BN 128
#define BK 16
#define SA 20          // padded smem row stride (floats); 80B rows keep 16B align
#define STAGES 4
#define TILE_FLOATS (BM * SA)            // 2560 floats per A or B tile
#define STAGE_FLOATS (2 * TILE_FLOATS)   // 5120
#define DSMEM_BYTES (STAGES * STAGE_FLOATS * 4)  // 81920

// ---------------- scratch (device globals; no allocation allowed) ----------
__device__ __align__(256) float g_x[Bb * 2560];        // [embeds | a]
__device__ __align__(256) float g_c1[Bb * 3584];       // [h_new | a | embeds]
__device__ __align__(256) float g_hb[Bb * Hh];         // dh @ W1h^T + b1
__device__ __align__(256) float g_part[8 * (Ss * Bb)]; // per-nblock partial scores
__device__ __align__(256) float g_alpha[Ss * Bb];      // softmax weights [s][b]
__device__ __align__(256) float g_gx[Bb * 3 * Hh];
__device__ __align__(256) float g_gh[Bb * 3 * Hh];

// ---------------- helpers ---------------------------------------------------
__device__ __forceinline__ uint32_t smem_u32(const void* p) {
    uint32_t a;
    asm("{ .reg .u64 t; cvta.to.shared.u64 t, %1; cvt.u32.u64 %0, t; }"
        : "=r"(a) : "l"(p));
    return a;
}

__device__ __forceinline__ uint32_t to_tf32_u(float x) {
    uint32_t u;
    asm("cvt.rna.tf32.f32 %0, %1;" : "=r"(u) : "f"(x));
    return u;
}

__device__ __forceinline__ void mma_tf32(float* c,
                                         uint32_t a0, uint32_t a1, uint32_t a2, uint32_t a3,
                                         uint32_t b0, uint32_t b1) {
    asm volatile(
        "mma.sync.aligned.m16n8k8.row.col.f32.tf32.tf32.f32 "
        "{%0,%1,%2,%3}, {%4,%5,%6,%7}, {%8,%9}, {%0,%1,%2,%3};"
        : "+f"(c[0]), "+f"(c[1]), "+f"(c[2]), "+f"(c[3])
        : "r"(a0), "r"(a1), "r"(a2), "r"(a3), "r"(b0), "r"(b1));
}

__device__ __forceinline__ void cp16(void* dst, const void* src) {
    asm volatile("cp.async.ca.shared.global [%0], [%1], 16;"
                 :: "r"(smem_u32(dst)), "l"(src));
}
__device__ __forceinline__ void cp_commit() {
    asm volatile("cp.async.commit_group;" ::: "memory");
}
template <int N>
__device__ __forceinline__ void cp_wait() {
    asm volatile("cp.async.wait_group %0;" :: "n"(N) : "memory");
}

__device__ __forceinline__ float tanh_fast(float x) {
    x = fminf(10.f, fmaxf(-10.f, x));
    const float t = __expf(2.f * x);
    return (t - 1.f) / (t + 1.f);
}

// Fill one stage (A tile + B tile) with cp.async. 256 threads, 2x16B chunks each
// per tile. Raw fp32 is staged; tf32 conversion happens at fragment-load time.
__device__ __forceinline__ void fill_stage(float* sA, float* sB,
                                           const float* __restrict__ A,
                                           const float* __restrict__ Bw,
                                           int m0, int n0, int lda, int ldb,
                                           int k0, int tid) {
#pragma unroll
    for (int h = 0; h < 2; h++) {
        const int c   = tid + h * 256;   // 0..511
        const int row = c >> 2;
        const int c4  = c & 3;
        cp16(sA + row * SA + c4 * 4, A  + (size_t)(m0 + row) * lda + k0 + c4 * 4);
        cp16(sB + row * SA + c4 * 4, Bw + (size_t)(n0 + row) * ldb + k0 + c4 * 4);
    }
}

// ---------------- tf32 GEMM (mma.sync + cp.async pipeline) ------------------
// out[M,N] = A[M,K] @ Bw[N,K]^T
// EPI 0: out[m*ldc+n] = acc + bias[n]
// EPI 1: partial[bx*M + m] = sum_n tanh(acc + hb[(m%128)*H + n]) * W2[n]
template <int EPI>
__global__ __launch_bounds__(256)
void gemm_tf32(const float* __restrict__ A, const float* __restrict__ Bw,
               const float* __restrict__ bias, float* __restrict__ out,
               int M, int K, int lda, int ldb, int ldc,
               const float* __restrict__ hb, const float* __restrict__ W2) {
    extern __shared__ __align__(16) float dyn[];
    __shared__ float red[BM][2];

    const int tid  = threadIdx.x;
    const int lane = tid & 31;
    const int wid  = tid >> 5;
    const int wm   = wid >> 1;   // 0..3  (32 rows each)
    const int wn   = wid & 1;    // 0..1  (64 cols each)
    const int r    = lane >> 2;
    const int q    = lane & 3;

    const int m0 = blockIdx.y * BM;
    const int n0 = blockIdx.x * BN;
    const int nK = K / BK;

    float c[2][8][4];
#pragma unroll
    for (int i = 0; i < 2; i++)
#pragma unroll
        for (int j = 0; j < 8; j++)
#pragma unroll
            for (int k = 0; k < 4; k++) c[i][j][k] = 0.f;

    // prologue: fill STAGES-1 stages
#pragma unroll
    for (int s = 0; s < STAGES - 1; s++) {
        fill_stage(dyn + s * STAGE_FLOATS, dyn + s * STAGE_FLOATS + TILE_FLOATS,
                   A, Bw, m0, n0, lda, ldb, s * BK, tid);
        cp_commit();
    }

    for (int kb = 0; kb < nK; kb++) {
        // prefetch stage kb+STAGES-1
        {
            const int pf = kb + STAGES - 1;
            if (pf < nK) {
                const int ps = pf & (STAGES - 1);
                fill_stage(dyn + ps * STAGE_FLOATS,
                           dyn + ps * STAGE_FLOATS + TILE_FLOATS,
                           A, Bw, m0, n0, lda, ldb, pf * BK, tid);
            }
            cp_commit();
        }
        cp_wait<STAGES - 2>();   // stage kb complete
        __syncthreads();

        const float* As = dyn + (kb & (STAGES - 1)) * STAGE_FLOATS;
        const float* Bs = As + TILE_FLOATS;

#pragma unroll
        for (int ks = 0; ks < 2; ks++) {
            const int k0 = ks * 8;
            uint32_t af[2][4];
#pragma unroll
            for (int mf = 0; mf < 2; mf++) {
                const int mb = (wm * 32 + mf * 16) * SA;
                af[mf][0] = to_tf32_u(As[mb + r * SA + k0 + q]);
                af[mf][1] = to_tf32_u(As[mb + (r + 8) * SA + k0 + q]);
                af[mf][2] = to_tf32_u(As[mb + r * SA + k0 + q + 4]);
                af[mf][3] = to_tf32_u(As[mb + (r + 8) * SA + k0 + q + 4]);
            }
#pragma unroll
            for (int nf = 0; nf < 8; nf++) {
                const int nb = (wn * 64 + nf * 8 + r) * SA;
                const uint32_t b0 = to_tf32_u(Bs[nb + k0 + q]);
                const uint32_t b1 = to_tf32_u(Bs[nb + k0 + q + 4]);
#pragma unroll
                for (int mf = 0; mf < 2; mf++)
                    mma_tf32(c[mf][nf], af[mf][0], af[mf][1], af[mf][2], af[mf][3], b0, b1);
            }
        }
        __syncthreads();   // all warps done with stage kb before it is refilled
    }

    if (EPI == 0) {
#pragma unroll
        for (int mf = 0; mf < 2; mf++)
#pragma unroll
            for (int rr = 0; rr < 2; rr++) {
                const int mg = m0 + wm * 32 + mf * 16 + rr * 8 + r;
#pragma unroll
                for (int nf = 0; nf < 8; nf++) {
                    const int ng = n0 + wn * 64 + nf * 8 + q * 2;
                    out[(size_t)mg * ldc + ng]     = c[mf][nf][rr * 2 + 0] + bias[ng];
                    out[(size_t)mg * ldc + ng + 1] = c[mf][nf][rr * 2 + 1] + bias[ng + 1];
                }
            }
    } else {
        // energy epilogue: tanh(acc + hb[b,n]) * W2[n], reduce over this CTA's n-range
        float rs[2][2];
#pragma unroll
        for (int mf = 0; mf < 2; mf++)
#pragma unroll
            for (int rr = 0; rr < 2; rr++) {
                const int row = wm * 32 + mf * 16 + rr * 8 + r; // == b
                float acc = 0.f;
#pragma unroll
                for (int nf = 0; nf < 8; nf++) {
                    const int ng = n0 + wn * 64 + nf * 8 + q * 2;
                    const float h0 = hb[row * Hh + ng];
                    const float h1 = hb[row * Hh + ng + 1];
                    acc += tanh_fast(c[mf][nf][rr * 2 + 0] + h0) * W2[ng];
                    acc += tanh_fast(c[mf][nf][rr * 2 + 1] + h1) * W2[ng + 1];
                }
                rs[mf][rr] = acc;
            }
#pragma unroll
        for (int mf = 0; mf < 2; mf++)
#pragma unroll
            for (int rr = 0; rr < 2; rr++) {
                rs[mf][rr] += __shfl_xor_sync(0xffffffffu, rs[mf][rr], 1);
                rs[mf][rr] += __shfl_xor_sync(0xffffffffu, rs[mf][rr], 2);
            }
        if (q == 0) {
#pragma unroll
            for (int mf = 0; mf < 2; mf++)
#pragma unroll
                for (int rr = 0; rr < 2; rr++)
                    red[wm * 32 + mf * 16 + rr * 8 + r][wn] = rs[mf][rr];
        }
        __syncthreads();
        if (tid < BM)
            out[(size_t)blockIdx.x * M + m0 + tid] = red[tid][0] + red[tid][1];
    }
}

// ---------------- small kernels ---------------------------------------------
__global__ void k_embed(const int* __restrict__ tl, const float* __restrict__ emb,
                        float* __restrict__ x, float* __restrict__ c1) {
    const int b = blockIdx.x;
    const int e = threadIdx.x; // 512
    const float v = emb[(size_t)tl[b] * Ee + e];
    x[b * 2560 + e] = v;
    c1[b * 3584 + 3072 + e] = v;
}

__global__ void k_softmax(const float* __restrict__ part, float* __restrict__ alpha) {
    const int b = blockIdx.x;
    const int s = threadIdx.x; // 128
    float sc = 0.f;
#pragma unroll
    for (int p = 0; p < 8; p++) sc += part[p * (Ss * Bb) + s * Bb + b];
    __shared__ float sh[Ss];
    sh[s] = sc; __syncthreads();
    for (int off = 64; off > 0; off >>= 1) {
        if (s < off) sh[s] = fmaxf(sh[s], sh[s + off]);
        __syncthreads();
    }
    const float mx = sh[0]; __syncthreads();
    const float e = __expf(sc - mx);
    sh[s] = e; __syncthreads();
    for (int off = 64; off > 0; off >>= 1) {
        if (s < off) sh[s] += sh[s + off];
        __syncthreads();
    }
    alpha[s * Bb + b] = e / sh[0];
}

__global__ void k_context(const float* __restrict__ enc, const float* __restrict__ alpha,
                          float* __restrict__ x, float* __restrict__ c1) {
    const int b = blockIdx.x;
    const int t = threadIdx.x; // 512
    float a0 = 0.f, a1 = 0.f, a2 = 0.f, a3 = 0.f;
    for (int s = 0; s < Ss; s++) {
        const float al = alpha[s * Bb + b];
        const float* e = enc + (size_t)(s * Bb + b) * 2048 + t;
        a0 += al * e[0];
        a1 += al * e[512];
        a2 += al * e[1024];
        a3 += al * e[1536];
    }
    x[b * 2560 + 512 + t]        = a0;  c1[b * 3584 + 1024 + t]        = a0;
    x[b * 2560 + 512 + 512 + t]  = a1;  c1[b * 3584 + 1024 + 512 + t]  = a1;
    x[b * 2560 + 512 + 1024 + t] = a2;  c1[b * 3584 + 1024 + 1024 + t] = a2;
    x[b * 2560 + 512 + 1536 + t] = a3;  c1[b * 3584 + 1024 + 1536 + t] = a3;
}

__global__ void k_gru(const float* __restrict__ dh, const float* __restrict__ gx,
                      const float* __restrict__ gh, float* __restrict__ hout,
                      float* __restrict__ c1) {
    const int b = blockIdx.x;
    const int h = threadIdx.x; // 1024
    const float xr = gx[b * 3072 + h],        hr = gh[b * 3072 + h];
    const float xz = gx[b * 3072 + 1024 + h], hz = gh[b * 3072 + 1024 + h];
    const float xn = gx[b * 3072 + 2048 + h], hn = gh[b * 3072 + 2048 + h];
    const float rg = 1.f / (1.f + __expf(-(xr + hr)));
    const float zg = 1.f / (1.f + __expf(-(xz + hz)));
    const float ng = tanh_fast(xn + rg * hn);
    const float hv = (1.f - zg) * ng + zg * dh[b * Hh + h];
    hout[b * Hh + h] = hv;
    c1[b * 3584 + h] = hv;
}

// ---------------- launch ----------------------------------------------------
extern "C" void kernel_launch(void* const* d_in, const int* in_sizes, int n_in,
                              void* d_out, int out_size) {
    const int*   tl   = (const int*)d_in[0];
    const float* dh   = (const float*)d_in[1];
    const float* enc  = (const float*)d_in[2];
    const float* emb  = (const float*)d_in[3];
    const float* W1   = (const float*)d_in[4];
    const float* b1   = (const float*)d_in[5];
    const float* W2   = (const float*)d_in[6];
    // d_in[7] = b2 (softmax-invariant, skipped)
    const float* Wih  = (const float*)d_in[8];
    const float* Whh  = (const float*)d_in[9];
    const float* bih  = (const float*)d_in[10];
    const float* bhh  = (const float*)d_in[11];
    const float* Wout = (const float*)d_in[12];
    const float* bout = (const float*)d_in[13];

    float* pred = (float*)d_out;                 // [128, 32000]
    float* hout = pred + (size_t)Bb * Vv;        // [128, 1024]

    float *x, *c1, *hb, *part, *alpha, *gx, *gh;
    cudaGetSymbolAddress((void**)&x,     g_x);
    cudaGetSymbolAddress((void**)&c1,    g_c1);
    cudaGetSymbolAddress((void**)&hb,    g_hb);
    cudaGetSymbolAddress((void**)&part,  g_part);
    cudaGetSymbolAddress((void**)&alpha, g_alpha);
    cudaGetSymbolAddress((void**)&gx,    g_gx);
    cudaGetSymbolAddress((void**)&gh,    g_gh);

    cudaFuncSetAttribute(gemm_tf32<0>, cudaFuncAttributeMaxDynamicSharedMemorySize, DSMEM_BYTES);
    cudaFuncSetAttribute(gemm_tf32<1>, cudaFuncAttributeMaxDynamicSharedMemorySize, DSMEM_BYTES);

    // 1) embeddings -> x[:, :512], c1[:, 3072:]
    k_embed<<<Bb, 512>>>(tl, emb, x, c1);

    // 2) hb = dh @ W1[:, 2048:3072]^T + b1   (M=128, N=1024, K=1024)
    gemm_tf32<0><<<dim3(8, 1), 256, DSMEM_BYTES>>>(dh, W1 + 2048, b1, hb,
                                                   Bb, Hh, Hh, 3 * Hh, Hh,
                                                   nullptr, nullptr);

    // 3) energy GEMM + fused tanh*W2 reduction (M=16384, N=1024, K=2048)
    //    grid.x = n-blocks (fastest) so co-resident CTAs share the enc A-band in L2
    gemm_tf32<1><<<dim3(8, 128), 256, DSMEM_BYTES>>>(enc, W1, nullptr, part,
                                                     Ss * Bb, 2 * Hh, 2 * Hh, 3 * Hh, 0,
                                                     hb, W2);

    // 4) combine partials + softmax over s  -> alpha[s][b]
    k_softmax<<<Bb, Ss>>>(part, alpha);

    // 5) context a = sum_s alpha * enc -> x[:, 512:], c1[:, 1024:3072]
    k_context<<<Bb, 512>>>(enc, alpha, x, c1);

    // 6) gx = x @ Wih^T + bih   (M=128, N=3072, K=2560)
    gemm_tf32<0><<<dim3(24, 1), 256, DSMEM_BYTES>>>(x, Wih, bih, gx,
                                                    Bb, 2560, 2560, 2560, 3 * Hh,
                                                    nullptr, nullptr);

    // 7) gh = dh @ Whh^T + bhh  (M=128, N=3072, K=1024)
    gemm_tf32<0><<<dim3(24, 1), 256, DSMEM_BYTES>>>(dh, Whh, bhh, gh,
                                                    Bb, Hh, Hh, Hh, 3 * Hh,
                                                    nullptr, nullptr);

    // 8) GRU elementwise -> h_new (output tail) and c1[:, :1024]
    k_gru<<<Bb, Hh>>>(dh, gx, gh, hout, c1);

    // 9) pred = c1 @ Wout^T + bout  (M=128, N=32000, K=3584)
    gemm_tf32<0><<<dim3(250, 1), 256, DSMEM_BYTES>>>(c1, Wout, bout, pred,
                                                     Bb, 3584, 3584, 3584, Vv,
                                                     nullptr, nullptr);
}

// round 4
// speedup vs baseline: 1.6501x; 1.0860x over previous
#include <cuda_runtime.h>
#include <cuda_bf16.h>
#include <cstdint>

// Problem constants
#define Bb 128
#define Ss 128
#define Hh 1024
#define Ee 512
#define Vv 32000

// GEMM tile config: CTA 128x128, 4 warps, warp tile 64x64, BK=16, 4 stages
#define BM 128
#define BN 128
#define BK 16
#define SA 20          // padded smem row stride (floats); 80B rows keep 16B align
#define STAGES 4
#define TILE_FLOATS (BM * SA)            // 2560 floats per A or B tile
#define STAGE_FLOATS (2 * TILE_FLOATS)   // 5120
#define DSMEM_BYTES (STAGES * STAGE_FLOATS * 4)  // 81920

// ---------------- scratch (device globals; no allocation allowed) ----------
__device__ __align__(256) float g_x[Bb * 2560];        // [embeds | a]
__device__ __align__(256) float g_c1[Bb * 3584];       // [h_new | a | embeds]
__device__ __align__(256) float g_hb[Bb * Hh];         // dh @ W1h^T + b1
__device__ __align__(256) float g_part[8 * (Ss * Bb)]; // per-nblock partial scores
__device__ __align__(256) float g_alpha[Ss * Bb];      // softmax weights [s][b]
__device__ __align__(256) float g_gx[Bb * 3 * Hh];
__device__ __align__(256) float g_gh[Bb * 3 * Hh];

// ---------------- helpers ---------------------------------------------------
__device__ __forceinline__ uint32_t smem_u32(const void* p) {
    uint32_t a;
    asm("{ .reg .u64 t; cvta.to.shared.u64 t, %1; cvt.u32.u64 %0, t; }"
        : "=r"(a) : "l"(p));
    return a;
}

__device__ __forceinline__ uint32_t to_tf32_u(float x) {
    uint32_t u;
    asm("cvt.rna.tf32.f32 %0, %1;" : "=r"(u) : "f"(x));
    return u;
}

__device__ __forceinline__ void mma_tf32(float* c,
                                         uint32_t a0, uint32_t a1, uint32_t a2, uint32_t a3,
                                         uint32_t b0, uint32_t b1) {
    asm volatile(
        "mma.sync.aligned.m16n8k8.row.col.f32.tf32.tf32.f32 "
        "{%0,%1,%2,%3}, {%4,%5,%6,%7}, {%8,%9}, {%0,%1,%2,%3};"
        : "+f"(c[0]), "+f"(c[1]), "+f"(c[2]), "+f"(c[3])
        : "r"(a0), "r"(a1), "r"(a2), "r"(a3), "r"(b0), "r"(b1));
}

__device__ __forceinline__ void cp16(void* dst, const void* src) {
    asm volatile("cp.async.ca.shared.global [%0], [%1], 16;"
                 :: "r"(smem_u32(dst)), "l"(src));
}
__device__ __forceinline__ void cp_commit() {
    asm volatile("cp.async.commit_group;" ::: "memory");
}
template <int N>
__device__ __forceinline__ void cp_wait() {
    asm volatile("cp.async.wait_group %0;" :: "n"(N) : "memory");
}

__device__ __forceinline__ float tanh_fast(float x) {
    x = fminf(10.f, fmaxf(-10.f, x));
    const float t = __expf(2.f * x);
    return (t - 1.f) / (t + 1.f);
}

// Fill one stage (A tile + B tile) with cp.async. 128 threads, 4x16B chunks each
// per tile. Raw fp32 staged; tf32 conversion happens at fragment-load time.
__device__ __forceinline__ void fill_stage(float* sA, float* sB,
                                           const float* __restrict__ A,
                                           const float* __restrict__ Bw,
                                           int m0, int n0, int lda, int ldb,
                                           int k0, int tid) {
#pragma unroll
    for (int h = 0; h < 4; h++) {
        const int c   = tid + h * 128;   // 0..511
        const int row = c >> 2;
        const int c4  = c & 3;
        cp16(sA + row * SA + c4 * 4, A  + (size_t)(m0 + row) * lda + k0 + c4 * 4);
        cp16(sB + row * SA + c4 * 4, Bw + (size_t)(n0 + row) * ldb + k0 + c4 * 4);
    }
}

// ---------------- tf32 GEMM (mma.sync + cp.async pipeline) ------------------
// out[M,N] = A[M,K] @ Bw[N,K]^T
// 4 warps, warp tile 64x64 (mf=4 x nf=8 fragments).
// EPI 0: out[m*ldc+n] = acc + bias[n]
// EPI 1: partial[bx*M + m] = sum_n tanh(acc + hb[(m%128)*H + n]) * W2[n]
template <int EPI>
__global__ __launch_bounds__(128)
void gemm_tf32(const float* __restrict__ A, const float* __restrict__ Bw,
               const float* __restrict__ bias, float* __restrict__ out,
               int M, int K, int lda, int ldb, int ldc,
               const float* __restrict__ hb, const float* __restrict__ W2) {
    extern __shared__ __align__(16) float dyn[];
    __shared__ float red[BM][2];

    const int tid  = threadIdx.x;
    const int lane = tid & 31;
    const int wid  = tid >> 5;
    const int wm   = wid >> 1;   // 0..1  (64 rows each)
    const int wn   = wid & 1;    // 0..1  (64 cols each)
    const int r    = lane >> 2;
    const int q    = lane & 3;

    const int m0 = blockIdx.y * BM;
    const int n0 = blockIdx.x * BN;
    const int nK = K / BK;

    float c[4][8][4];
#pragma unroll
    for (int i = 0; i < 4; i++)
#pragma unroll
        for (int j = 0; j < 8; j++)
#pragma unroll
            for (int k = 0; k < 4; k++) c[i][j][k] = 0.f;

    // prologue: fill STAGES-1 stages
#pragma unroll
    for (int s = 0; s < STAGES - 1; s++) {
        fill_stage(dyn + s * STAGE_FLOATS, dyn + s * STAGE_FLOATS + TILE_FLOATS,
                   A, Bw, m0, n0, lda, ldb, s * BK, tid);
        cp_commit();
    }

    for (int kb = 0; kb < nK; kb++) {
        cp_wait<STAGES - 2>();   // stage kb complete
        __syncthreads();         // also proves all threads finished stage kb-1

        // refill the stage consumed at kb-1 with k-block kb+STAGES-1
        {
            const int pf = kb + STAGES - 1;
            if (pf < nK) {
                const int ps = pf & (STAGES - 1);
                fill_stage(dyn + ps * STAGE_FLOATS,
                           dyn + ps * STAGE_FLOATS + TILE_FLOATS,
                           A, Bw, m0, n0, lda, ldb, pf * BK, tid);
            }
            cp_commit();
        }

        const float* As = dyn + (kb & (STAGES - 1)) * STAGE_FLOATS;
        const float* Bs = As + TILE_FLOATS;

#pragma unroll
        for (int ks = 0; ks < 2; ks++) {
            const int k0 = ks * 8;
            uint32_t af[4][4];
#pragma unroll
            for (int mf = 0; mf < 4; mf++) {
                const int mb = (wm * 64 + mf * 16) * SA;
                af[mf][0] = to_tf32_u(As[mb + r * SA + k0 + q]);
                af[mf][1] = to_tf32_u(As[mb + (r + 8) * SA + k0 + q]);
                af[mf][2] = to_tf32_u(As[mb + r * SA + k0 + q + 4]);
                af[mf][3] = to_tf32_u(As[mb + (r + 8) * SA + k0 + q + 4]);
            }
#pragma unroll
            for (int nf = 0; nf < 8; nf++) {
                const int nb = (wn * 64 + nf * 8 + r) * SA;
                const uint32_t b0 = to_tf32_u(Bs[nb + k0 + q]);
                const uint32_t b1 = to_tf32_u(Bs[nb + k0 + q + 4]);
#pragma unroll
                for (int mf = 0; mf < 4; mf++)
                    mma_tf32(c[mf][nf], af[mf][0], af[mf][1], af[mf][2], af[mf][3], b0, b1);
            }
        }
    }

    if (EPI == 0) {
#pragma unroll
        for (int mf = 0; mf < 4; mf++)
#pragma unroll
            for (int rr = 0; rr < 2; rr++) {
                const int mg = m0 + wm * 64 + mf * 16 + rr * 8 + r;
#pragma unroll
                for (int nf = 0; nf < 8; nf++) {
                    const int ng = n0 + wn * 64 + nf * 8 + q * 2;
                    float2 v;
                    v.x = c[mf][nf][rr * 2 + 0] + bias[ng];
                    v.y = c[mf][nf][rr * 2 + 1] + bias[ng + 1];
                    *(float2*)&out[(size_t)mg * ldc + ng] = v;
                }
            }
    } else {
        // energy epilogue: tanh(acc + hb[b,n]) * W2[n], reduce over this CTA's n-range
        float rs[4][2];
#pragma unroll
        for (int mf = 0; mf < 4; mf++)
#pragma unroll
            for (int rr = 0; rr < 2; rr++) {
                const int row = wm * 64 + mf * 16 + rr * 8 + r; // == b
                float acc = 0.f;
#pragma unroll
                for (int nf = 0; nf < 8; nf++) {
                    const int ng = n0 + wn * 64 + nf * 8 + q * 2;
                    const float h0 = hb[row * Hh + ng];
                    const float h1 = hb[row * Hh + ng + 1];
                    acc += tanh_fast(c[mf][nf][rr * 2 + 0] + h0) * W2[ng];
                    acc += tanh_fast(c[mf][nf][rr * 2 + 1] + h1) * W2[ng + 1];
                }
                rs[mf][rr] = acc;
            }
#pragma unroll
        for (int mf = 0; mf < 4; mf++)
#pragma unroll
            for (int rr = 0; rr < 2; rr++) {
                rs[mf][rr] += __shfl_xor_sync(0xffffffffu, rs[mf][rr], 1);
                rs[mf][rr] += __shfl_xor_sync(0xffffffffu, rs[mf][rr], 2);
            }
        if (q == 0) {
#pragma unroll
            for (int mf = 0; mf < 4; mf++)
#pragma unroll
                for (int rr = 0; rr < 2; rr++)
                    red[wm * 64 + mf * 16 + rr * 8 + r][wn] = rs[mf][rr];
        }
        __syncthreads();
        if (tid < BM)
            out[(size_t)blockIdx.x * M + m0 + tid] = red[tid][0] + red[tid][1];
    }
}

// ---------------- small kernels ---------------------------------------------
__global__ void k_embed(const int* __restrict__ tl, const float* __restrict__ emb,
                        float* __restrict__ x, float* __restrict__ c1) {
    const int b = blockIdx.x;
    const int e = threadIdx.x; // 512
    const float v = emb[(size_t)tl[b] * Ee + e];
    x[b * 2560 + e] = v;
    c1[b * 3584 + 3072 + e] = v;
}

__global__ void k_softmax(const float* __restrict__ part, float* __restrict__ alpha) {
    const int b = blockIdx.x;
    const int s = threadIdx.x; // 128
    float sc = 0.f;
#pragma unroll
    for (int p = 0; p < 8; p++) sc += part[p * (Ss * Bb) + s * Bb + b];
    __shared__ float sh[Ss];
    sh[s] = sc; __syncthreads();
    for (int off = 64; off > 0; off >>= 1) {
        if (s < off) sh[s] = fmaxf(sh[s], sh[s + off]);
        __syncthreads();
    }
    const float mx = sh[0]; __syncthreads();
    const float e = __expf(sc - mx);
    sh[s] = e; __syncthreads();
    for (int off = 64; off > 0; off >>= 1) {
        if (s < off) sh[s] += sh[s + off];
        __syncthreads();
    }
    alpha[s * Bb + b] = e / sh[0];
}

__global__ void k_context(const float* __restrict__ enc, const float* __restrict__ alpha,
                          float* __restrict__ x, float* __restrict__ c1) {
    const int b = blockIdx.x;
    const int t = threadIdx.x; // 512
    float a0 = 0.f, a1 = 0.f, a2 = 0.f, a3 = 0.f;
    for (int s = 0; s < Ss; s++) {
        const float al = alpha[s * Bb + b];
        const float* e = enc + (size_t)(s * Bb + b) * 2048 + t;
        a0 += al * e[0];
        a1 += al * e[512];
        a2 += al * e[1024];
        a3 += al * e[1536];
    }
    x[b * 2560 + 512 + t]        = a0;  c1[b * 3584 + 1024 + t]        = a0;
    x[b * 2560 + 512 + 512 + t]  = a1;  c1[b * 3584 + 1024 + 512 + t]  = a1;
    x[b * 2560 + 512 + 1024 + t] = a2;  c1[b * 3584 + 1024 + 1024 + t] = a2;
    x[b * 2560 + 512 + 1536 + t] = a3;  c1[b * 3584 + 1024 + 1536 + t] = a3;
}

__global__ void k_gru(const float* __restrict__ dh, const float* __restrict__ gx,
                      const float* __restrict__ gh, float* __restrict__ hout,
                      float* __restrict__ c1) {
    const int b = blockIdx.x;
    const int h = threadIdx.x; // 1024
    const float xr = gx[b * 3072 + h],        hr = gh[b * 3072 + h];
    const float xz = gx[b * 3072 + 1024 + h], hz = gh[b * 3072 + 1024 + h];
    const float xn = gx[b * 3072 + 2048 + h], hn = gh[b * 3072 + 2048 + h];
    const float rg = 1.f / (1.f + __expf(-(xr + hr)));
    const float zg = 1.f / (1.f + __expf(-(xz + hz)));
    const float ng = tanh_fast(xn + rg * hn);
    const float hv = (1.f - zg) * ng + zg * dh[b * Hh + h];
    hout[b * Hh + h] = hv;
    c1[b * 3584 + h] = hv;
}

// ---------------- launch ----------------------------------------------------
extern "C" void kernel_launch(void* const* d_in, const int* in_sizes, int n_in,
                              void* d_out, int out_size) {
    const int*   tl   = (const int*)d_in[0];
    const float* dh   = (const float*)d_in[1];
    const float* enc  = (const float*)d_in[2];
    const float* emb  = (const float*)d_in[3];
    const float* W1   = (const float*)d_in[4];
    const float* b1   = (const float*)d_in[5];
    const float* W2   = (const float*)d_in[6];
    // d_in[7] = b2 (softmax-invariant, skipped)
    const float* Wih  = (const float*)d_in[8];
    const float* Whh  = (const float*)d_in[9];
    const float* bih  = (const float*)d_in[10];
    const float* bhh  = (const float*)d_in[11];
    const float* Wout = (const float*)d_in[12];
    const float* bout = (const float*)d_in[13];

    float* pred = (float*)d_out;                 // [128, 32000]
    float* hout = pred + (size_t)Bb * Vv;        // [128, 1024]

    float *x, *c1, *hb, *part, *alpha, *gx, *gh;
    cudaGetSymbolAddress((void**)&x,     g_x);
    cudaGetSymbolAddress((void**)&c1,    g_c1);
    cudaGetSymbolAddress((void**)&hb,    g_hb);
    cudaGetSymbolAddress((void**)&part,  g_part);
    cudaGetSymbolAddress((void**)&alpha, g_alpha);
    cudaGetSymbolAddress((void**)&gx,    g_gx);
    cudaGetSymbolAddress((void**)&gh,    g_gh);

    cudaFuncSetAttribute(gemm_tf32<0>, cudaFuncAttributeMaxDynamicSharedMemorySize, DSMEM_BYTES);
    cudaFuncSetAttribute(gemm_tf32<1>, cudaFuncAttributeMaxDynamicSharedMemorySize, DSMEM_BYTES);

    // 1) embeddings -> x[:, :512], c1[:, 3072:]
    k_embed<<<Bb, 512>>>(tl, emb, x, c1);

    // 2) hb = dh @ W1[:, 2048:3072]^T + b1   (M=128, N=1024, K=1024)
    gemm_tf32<0><<<dim3(8, 1), 128, DSMEM_BYTES>>>(dh, W1 + 2048, b1, hb,
                                                   Bb, Hh, Hh, 3 * Hh, Hh,
                                                   nullptr, nullptr);

    // 3) energy GEMM + fused tanh*W2 reduction (M=16384, N=1024, K=2048)
    gemm_tf32<1><<<dim3(8, 128), 128, DSMEM_BYTES>>>(enc, W1, nullptr, part,
                                                     Ss * Bb, 2 * Hh, 2 * Hh, 3 * Hh, 0,
                                                     hb, W2);

    // 4) combine partials + softmax over s  -> alpha[s][b]
    k_softmax<<<Bb, Ss>>>(part, alpha);

    // 5) context a = sum_s alpha * enc -> x[:, 512:], c1[:, 1024:3072]
    k_context<<<Bb, 512>>>(enc, alpha, x, c1);

    // 6) gx = x @ Wih^T + bih   (M=128, N=3072, K=2560)
    gemm_tf32<0><<<dim3(24, 1), 128, DSMEM_BYTES>>>(x, Wih, bih, gx,
                                                    Bb, 2560, 2560, 2560, 3 * Hh,
                                                    nullptr, nullptr);

    // 7) gh = dh @ Whh^T + bhh  (M=128, N=3072, K=1024)
    gemm_tf32<0><<<dim3(24, 1), 128, DSMEM_BYTES>>>(dh, Whh, bhh, gh,
                                                    Bb, Hh, Hh, Hh, 3 * Hh,
                                                    nullptr, nullptr);

    // 8) GRU elementwise -> h_new (output tail) and c1[:, :1024]
    k_gru<<<Bb, Hh>>>(dh, gx, gh, hout, c1);

    // 9) pred = c1 @ Wout^T + bout  (M=128, N=32000, K=3584)
    gemm_tf32<0><<<dim3(250, 1), 128, DSMEM_BYTES>>>(c1, Wout, bout, pred,
                                                     Bb, 3584, 3584, 3584, Vv,
                                                     nullptr, nullptr);
}